// round 9
// baseline (speedup 1.0000x reference)
#include <cuda_runtime.h>
#include <cstdint>

#define NQ   14
#define TPB  512
typedef unsigned long long ull;

__device__ __forceinline__ int pf_(int x) {
    x ^= x >> 1; x ^= x >> 2; x ^= x >> 4; x ^= x >> 8;
    return x;
}

__device__ __forceinline__ ull f2mul(ull a, ull b) {
    ull r; asm("mul.rn.f32x2 %0,%1,%2;" : "=l"(r) : "l"(a), "l"(b)); return r;
}
__device__ __forceinline__ ull f2fma(ull a, ull b, ull c) {
    ull r; asm("fma.rn.f32x2 %0,%1,%2,%3;" : "=l"(r) : "l"(a), "l"(b), "l"(c)); return r;
}
__device__ __forceinline__ ull pk2(float x, float y) {
    ull r; asm("mov.b64 %0,{%1,%2};" : "=l"(r) : "f"(x), "f"(y)); return r;
}
__device__ __forceinline__ float2 upk(ull a) {
    float2 r; asm("mov.b64 {%0,%1},%2;" : "=f"(r.x), "=f"(r.y) : "l"(a)); return r;
}
__device__ __forceinline__ ull swp(ull a) { float2 t = upk(a); return pk2(t.y, t.x); }
__device__ __forceinline__ ull bc(float x) { return pk2(x, x); }

__device__ __forceinline__ float2 cmul_s(float2 a, float2 b) {
    return make_float2(a.x * b.x - a.y * b.y, a.x * b.y + a.y * b.x);
}

#define SPAD 9216   // 8192 pairs + 2 pad per 16: A(p) = p + 2*(p>>4)

__global__ void __launch_bounds__(TPB, 1)
qsim_kernel(const float* __restrict__ sb, const float* __restrict__ vp,
            const float* __restrict__ hw, const float* __restrict__ hb,
            float* __restrict__ out)
{
    extern __shared__ unsigned char smraw[];
    ull*    sRe   = (ull*)smraw;             // 9216
    ull*    sIm   = sRe + SPAD;              // 9216
    ull*    PloRe = sIm + SPAD;              // 2*64 (layers 0,1), [L][r*4+c]
    ull*    PloIm = PloRe + 128;             // 2*64
    ull*    Wlo2  = PloIm + 128;             // 64 (scalar view Wlo[128])
    float*  tanw  = (float*)(Wlo2 + 64);     // 48 (42 used)
    float*  cosw  = tanw + 48;               // 48 (42 used)
    float2* phw   = (float2*)(cosw + 48);    // 48 (28 used)
    float*  PhiRe = (float*)(phw + 48);      // 256
    float*  PhiIm = PhiRe + 256;             // 256
    float*  cx    = PhiIm + 256;             // 16
    float*  sx    = cx + 16;                 // 16
    float*  Whi   = sx + 16;                 // 128
    float*  red   = Whi + 128;               // 16
    float*  WloF  = (float*)Wlo2;

    const int t = threadIdx.x;
    const int b = blockIdx.x;

    // ---- stage 1: parameter staging ----
    if (t < NQ) {
        float s, c; sincosf(0.5f * sb[b * NQ + t], &s, &c);
        cx[t] = c; sx[t] = s;
    }
    if (t >= 64 && t < 64 + 3 * NQ) {
        int lw = t - 64;
        float sa, ca;
        sincosf(0.5f * vp[lw * 3 + 0], &sa, &ca);
        tanw[lw] = __fdividef(sa, ca);
        cosw[lw] = ca;
        if (lw < 2 * NQ) {
            float sp, cp;
            sincosf(vp[lw * 3 + 1], &sp, &cp);
            phw[lw] = make_float2(cp, sp);
        }
    }
    __syncthreads();

    // ---- stage 2: LUT builds (phases for L=0,1; cos^2-scaled weights) ----
    if (t < 256) {
        int L = t >> 7, v = t & 127;
        float2 pl = make_float2(1.f, 0.f), ph = make_float2(1.f, 0.f);
        #pragma unroll
        for (int k = 0; k < 7; k++) {
            if ((v >> k) & 1) {
                pl = cmul_s(pl, phw[L * NQ + (13 - k)]);
                ph = cmul_s(ph, phw[L * NQ + (6 - k)]);
            }
        }
        PhiRe[t] = ph.x; PhiIm[t] = ph.y;
        int c = v >> 5, r = (v >> 1) & 15, b0 = v & 1;
        ((float*)PloRe)[2 * (L * 64 + r * 4 + c) + b0] = pl.x;
        ((float*)PloIm)[2 * (L * 64 + r * 4 + c) + b0] = pl.y;
    } else {
        float prod = 1.f;
        #pragma unroll
        for (int k = 0; k < 3 * NQ; k++) prod *= cosw[k];
        prod *= prod;
        if (t < 384) {
            int v = t - 256; float acc = 0.f;
            #pragma unroll
            for (int k = 0; k < 7; k++)
                acc += hw[13 - k] * (1.f - 2.f * (float)((v >> k) & 1));
            WloF[v] = acc * prod;
        } else {
            int v = t - 384; float acc = 0.f;
            #pragma unroll
            for (int k = 0; k < 7; k++)
                acc += hw[6 - k] * (1.f - 2.f * (float)((v >> k) & 1));
            Whi[v] = acc * prod;
        }
    }

    ull vre[16], vim[16];

    // tangent-form RY on tile bit lb: u0' = u0 - t*u1 ; u1' = u1 + t*u0
    auto applyW = [&](float tg, int lb) {
        ull tp = bc(tg), tn = bc(-tg);
        #pragma unroll
        for (int m = 0; m < 8; m++) {
            int l0 = ((m >> lb) << (lb + 1)) | (m & ((1 << lb) - 1));
            int l1 = l0 | (1 << lb);
            ull r0 = f2fma(tn, vre[l1], vre[l0]);
            ull r1 = f2fma(tp, vre[l0], vre[l1]);
            vre[l0] = r0; vre[l1] = r1;
            ull i0 = f2fma(tn, vim[l1], vim[l0]);
            ull i1 = f2fma(tp, vim[l0], vim[l1]);
            vim[l0] = i0; vim[l1] = i1;
        }
    };

    // pass bases under pad A(p) = p + 2*(p>>4)
    const int b1 = t + 2 * (t >> 4);                                // + 576*r
    const int b2 = 576 * (t >> 5) + (t & 31) + 2 * ((t >> 4) & 1);  // + 36*r
    const int b3 = 36 * (t >> 1) + (t & 1);                         // + 2r + 2*(r>>3)
    const int b4 = 18 * t;                                          // + r (even!)

    // ---- init: closed-form RX + layer-0 wires 0..3 (tan form) ----
    {
        float mt = 1.f;
        #pragma unroll
        for (int k = 0; k < 9; k++)
            mt *= ((t >> k) & 1) ? sx[12 - k] : cx[12 - k];
        int pt = __popc(t);
        #pragma unroll
        for (int r = 0; r < 16; r++) {
            float mr = mt;
            #pragma unroll
            for (int m = 0; m < 4; m++)
                mr *= ((r >> m) & 1) ? sx[3 - m] : cx[3 - m];
            int pr = pt + __popc(r);
            float m0 = mr * cx[13], m1 = mr * sx[13];
            int k0 = pr & 3, k1 = (pr + 1) & 3;
            float re0 = (k0 == 0) ? m0 : ((k0 == 2) ? -m0 : 0.f);
            float im0 = (k0 == 1) ? -m0 : ((k0 == 3) ? m0 : 0.f);
            float re1 = (k1 == 0) ? m1 : ((k1 == 2) ? -m1 : 0.f);
            float im1 = (k1 == 1) ? -m1 : ((k1 == 3) ? m1 : 0.f);
            vre[r] = pk2(re0, re1); vim[r] = pk2(im0, im1);
        }
        __syncthreads();   // stage-2 LUT writes complete
        #pragma unroll
        for (int lb = 0; lb < 4; lb++) applyW(tanw[3 - lb], lb);
        #pragma unroll
        for (int r = 0; r < 16; r++) { sRe[b1 + 576 * r] = vre[r]; sIm[b1 + 576 * r] = vim[r]; }
    }
    __syncthreads();

    #pragma unroll 1
    for (int L = 0; L < 3; L++) {
        // ---- P2: wires 4..7 (cross-warp handoff happened at the block sync) ----
        {
            #pragma unroll
            for (int r = 0; r < 16; r++) { vre[r] = sRe[b2 + 36 * r]; vim[r] = sIm[b2 + 36 * r]; }
            #pragma unroll
            for (int lb = 0; lb < 4; lb++) applyW(tanw[L * NQ + (7 - lb)], lb);
            #pragma unroll
            for (int r = 0; r < 16; r++) { sRe[b2 + 36 * r] = vre[r]; sIm[b2 + 36 * r] = vim[r]; }
        }
        __syncwarp(0xffffffffu);   // P2->P3 exchange is warp-local (pair bits 12..9 = warp id)

        // ---- P3: wires 8..11 ----
        {
            #pragma unroll
            for (int r = 0; r < 16; r++) {
                int o = b3 + 2 * r + 2 * (r >> 3);
                vre[r] = sRe[o]; vim[r] = sIm[o];
            }
            #pragma unroll
            for (int lb = 0; lb < 4; lb++) applyW(tanw[L * NQ + (11 - lb)], lb);
            #pragma unroll
            for (int r = 0; r < 16; r++) {
                int o = b3 + 2 * r + 2 * (r >> 3);
                sRe[o] = vre[r]; sIm[o] = vim[r];
            }
        }
        __syncwarp(0xffffffffu);   // P3->P4 exchange is warp-local

        // ---- P4: wires 12,13; phase for L<2; fused measurement at L=2 ----
        {
            const ulonglong2* pR = (const ulonglong2*)(sRe + b4);
            const ulonglong2* pI = (const ulonglong2*)(sIm + b4);
            #pragma unroll
            for (int k = 0; k < 8; k++) {
                ulonglong2 a = pR[k]; vre[2 * k] = a.x; vre[2 * k + 1] = a.y;
                ulonglong2 c = pI[k]; vim[2 * k] = c.x; vim[2 * k + 1] = c.y;
            }
            applyW(tanw[L * NQ + 12], 0);
            {
                ull tm = pk2(-tanw[L * NQ + 13], tanw[L * NQ + 13]);
                #pragma unroll
                for (int r = 0; r < 16; r++) {
                    vre[r] = f2fma(tm, swp(vre[r]), vre[r]);
                    vim[r] = f2fma(tm, swp(vim[r]), vim[r]);
                }
            }
            if (L < 2) {
                float fr = PhiRe[L * 128 + (t >> 2)];
                float fi = PhiIm[L * 128 + (t >> 2)];
                ull fr2 = bc(fr), fi2 = bc(fi), nfi2 = bc(-fi), n1 = bc(-1.f);
                const int c = t & 3;
                #pragma unroll
                for (int r = 0; r < 16; r++) {
                    ull pr2 = PloRe[L * 64 + r * 4 + c];
                    ull pi2 = PloIm[L * 64 + r * 4 + c];
                    ull cr  = f2fma(fr2, pr2, f2mul(nfi2, pi2));
                    ull ci  = f2fma(fr2, pi2, f2mul(fi2, pr2));
                    ull nci = f2mul(n1, ci);
                    ull re = vre[r], im = vim[r];
                    vre[r] = f2fma(cr, re, f2mul(nci, im));
                    vim[r] = f2fma(cr, im, f2mul(ci,  re));
                }
                ulonglong2* qR = (ulonglong2*)(sRe + b4);
                ulonglong2* qI = (ulonglong2*)(sIm + b4);
                #pragma unroll
                for (int k = 0; k < 8; k++) {
                    qR[k] = make_ulonglong2(vre[2 * k], vre[2 * k + 1]);
                    qI[k] = make_ulonglong2(vim[2 * k], vim[2 * k + 1]);
                }
            } else {
                // ---- measurement from registers (chain folded, scaled W) ----
                const int ftt = pf_(t << 5);
                const float whi = Whi[ftt >> 7];
                ull acc2 = bc(0.f);
                #pragma unroll
                for (int k = 0; k < 16; k++) {
                    ull pr2 = f2fma(vim[k], vim[k], f2mul(vre[k], vre[k]));
                    int f0 = (ftt ^ pf_(k << 1)) & 127;
                    float w0 = WloF[f0]     + whi;
                    float w1 = WloF[f0 ^ 1] + whi;
                    acc2 = f2fma(pr2, pk2(w0, w1), acc2);
                }
                float2 ac = upk(acc2);
                float acc = ac.x + ac.y;
                #pragma unroll
                for (int o = 16; o > 0; o >>= 1)
                    acc += __shfl_xor_sync(0xffffffffu, acc, o);
                if ((t & 31) == 0) red[t >> 5] = acc;
                __syncthreads();
                if (t == 0) {
                    float s = 0.f;
                    #pragma unroll
                    for (int w = 0; w < TPB / 32; w++) s += red[w];
                    out[b] = s + hb[0];
                }
            }
        }

        if (L < 2) {
            __syncthreads();   // P4 writes visible block-wide before global fold
            // ---- P1' of next layer with CNOT-chain fold ----
            const int e  = t ^ (t >> 1);
            const int eh = e >> 4;
            #pragma unroll
            for (int r = 0; r < 16; r++) {
                const int C = (r << 1) ^ r;          // compile-time
                int q = e ^ (C << 8);
                int a = q + 2 * (eh ^ (C << 4));
                vre[r] = sRe[a]; vim[r] = sIm[a];
            }
            if (t & 1) {
                #pragma unroll
                for (int r = 0; r < 16; r++) { vre[r] = swp(vre[r]); vim[r] = swp(vim[r]); }
            }
            #pragma unroll
            for (int lb = 0; lb < 4; lb++) applyW(tanw[(L + 1) * NQ + (3 - lb)], lb);
            __syncthreads();   // all fold reads done before rewrites
            #pragma unroll
            for (int r = 0; r < 16; r++) { sRe[b1 + 576 * r] = vre[r]; sIm[b1 + 576 * r] = vim[r]; }
            __syncthreads();
        }
    }
}

extern "C" void kernel_launch(void* const* d_in, const int* in_sizes, int n_in,
                              void* d_out, int out_size) {
    const float* sb = (const float*)d_in[0];
    const float* vp = (const float*)d_in[1];
    const float* hw = (const float*)d_in[2];
    const float* hb = (const float*)d_in[3];
    float* out = (float*)d_out;

    const int B = in_sizes[0] / NQ;
    const size_t smem = (size_t)(SPAD * 2 + 128 * 2 + 64) * 8   // sRe,sIm,Plo*,Wlo2
                      + (48 + 48) * 4 + 48 * 8                  // tanw,cosw,phw
                      + (256 * 2 + 32 + 128 + 16) * 4;          // PhiRe/Im,cx,sx,Whi,red
    cudaFuncSetAttribute(qsim_kernel,
                         cudaFuncAttributeMaxDynamicSharedMemorySize, (int)smem);
    qsim_kernel<<<B, TPB, smem>>>(sb, vp, hw, hb, out);
}

// round 10
// speedup vs baseline: 1.1377x; 1.1377x over previous
#include <cuda_runtime.h>
#include <cstdint>

#define NQ   14
#define TPB  512
typedef unsigned long long ull;

__device__ __forceinline__ int pf_(int x) {
    x ^= x >> 1; x ^= x >> 2; x ^= x >> 4; x ^= x >> 8;
    return x;
}

__device__ __forceinline__ ull f2mul(ull a, ull b) {
    ull r; asm("mul.rn.f32x2 %0,%1,%2;" : "=l"(r) : "l"(a), "l"(b)); return r;
}
__device__ __forceinline__ ull f2fma(ull a, ull b, ull c) {
    ull r; asm("fma.rn.f32x2 %0,%1,%2,%3;" : "=l"(r) : "l"(a), "l"(b), "l"(c)); return r;
}
__device__ __forceinline__ ull pk2(float x, float y) {
    ull r; asm("mov.b64 %0,{%1,%2};" : "=l"(r) : "f"(x), "f"(y)); return r;
}
__device__ __forceinline__ float2 upk(ull a) {
    float2 r; asm("mov.b64 {%0,%1},%2;" : "=f"(r.x), "=f"(r.y) : "l"(a)); return r;
}
__device__ __forceinline__ ull swp(ull a) { float2 t = upk(a); return pk2(t.y, t.x); }
__device__ __forceinline__ ull bc(float x) { return pk2(x, x); }

__device__ __forceinline__ float2 cmul_s(float2 a, float2 b) {
    return make_float2(a.x * b.x - a.y * b.y, a.x * b.y + a.y * b.x);
}

#define SPAD 8704   // 8192 pairs + 512 pad (1 per 16), pad A(p)=p+(p>>4)

__global__ void __launch_bounds__(TPB, 1)
qsim_kernel(const float* __restrict__ sb, const float* __restrict__ vp,
            const float* __restrict__ hw, const float* __restrict__ hb,
            float* __restrict__ out)
{
    extern __shared__ unsigned char smraw[];
    ull*    sRe   = (ull*)smraw;             // 8704
    ull*    sIm   = sRe + SPAD;              // 8704
    ull*    PloRe = sIm + SPAD;              // 2*64 (layers 0,1), [L][r*4+c]
    ull*    PloIm = PloRe + 128;             // 2*64
    ull*    Wlo2  = PloIm + 128;             // 64 (scalar view Wlo[128])
    float*  tanw  = (float*)(Wlo2 + 64);     // 48 (42 used)
    float*  cosw  = tanw + 48;               // 48 (42 used)
    float2* phw   = (float2*)(cosw + 48);    // 48 (28 used)
    float*  PhiRe = (float*)(phw + 48);      // 256
    float*  PhiIm = PhiRe + 256;             // 256
    float*  cx    = PhiIm + 256;             // 16
    float*  sx    = cx + 16;                 // 16
    float*  Whi   = sx + 16;                 // 128
    float*  red   = Whi + 128;               // 16
    float*  WloF  = (float*)Wlo2;

    const int t = threadIdx.x;
    const int b = blockIdx.x;

    // ---- stage 1: parameter staging ----
    if (t < NQ) {
        float s, c; sincosf(0.5f * sb[b * NQ + t], &s, &c);
        cx[t] = c; sx[t] = s;
    }
    if (t >= 64 && t < 64 + 3 * NQ) {
        int lw = t - 64;
        float sa, ca;
        sincosf(0.5f * vp[lw * 3 + 0], &sa, &ca);
        tanw[lw] = __fdividef(sa, ca);
        cosw[lw] = ca;
        if (lw < 2 * NQ) {
            float sp, cp;
            sincosf(vp[lw * 3 + 1], &sp, &cp);
            phw[lw] = make_float2(cp, sp);
        }
    }
    __syncthreads();

    // ---- stage 2: LUT builds (phases for L=0,1; cos^2-scaled weights) ----
    if (t < 256) {
        int L = t >> 7, v = t & 127;
        float2 pl = make_float2(1.f, 0.f), ph = make_float2(1.f, 0.f);
        #pragma unroll
        for (int k = 0; k < 7; k++) {
            if ((v >> k) & 1) {
                pl = cmul_s(pl, phw[L * NQ + (13 - k)]);
                ph = cmul_s(ph, phw[L * NQ + (6 - k)]);
            }
        }
        PhiRe[t] = ph.x; PhiIm[t] = ph.y;
        int c = v >> 5, r = (v >> 1) & 15, b0 = v & 1;
        ((float*)PloRe)[2 * (L * 64 + r * 4 + c) + b0] = pl.x;
        ((float*)PloIm)[2 * (L * 64 + r * 4 + c) + b0] = pl.y;
    } else {
        // global scale = (prod of all 42 cos)^2, folded into weight LUTs
        float prod = 1.f;
        #pragma unroll
        for (int k = 0; k < 3 * NQ; k++) prod *= cosw[k];
        prod *= prod;
        if (t < 384) {
            int v = t - 256; float acc = 0.f;
            #pragma unroll
            for (int k = 0; k < 7; k++)
                acc += hw[13 - k] * (1.f - 2.f * (float)((v >> k) & 1));
            WloF[v] = acc * prod;
        } else {
            int v = t - 384; float acc = 0.f;
            #pragma unroll
            for (int k = 0; k < 7; k++)
                acc += hw[6 - k] * (1.f - 2.f * (float)((v >> k) & 1));
            Whi[v] = acc * prod;
        }
    }

    ull vre[16], vim[16];

    // tangent-form RY on tile bit lb: u0' = u0 - t*u1 ; u1' = u1 + t*u0
    auto applyW = [&](float tg, int lb) {
        ull tp = bc(tg), tn = bc(-tg);
        #pragma unroll
        for (int m = 0; m < 8; m++) {
            int l0 = ((m >> lb) << (lb + 1)) | (m & ((1 << lb) - 1));
            int l1 = l0 | (1 << lb);
            ull r0 = f2fma(tn, vre[l1], vre[l0]);
            ull r1 = f2fma(tp, vre[l0], vre[l1]);
            vre[l0] = r0; vre[l1] = r1;
            ull i0 = f2fma(tn, vim[l1], vim[l0]);
            ull i1 = f2fma(tp, vim[l0], vim[l1]);
            vim[l0] = i0; vim[l1] = i1;
        }
    };

    // affine pass bases (padding A(p) = p + (p>>4))
    const int b1 = t + (t >> 4);                               // + 544*r
    const int b2 = (t >> 5) * 544 + (t & 31) + ((t >> 4) & 1); // + 34*r
    const int b3 = 34 * (t >> 1) + (t & 1);                    // + 2r + (r>>3)
    const int b4 = 17 * t;                                     // + r

    // ---- init: closed-form RX + layer-0 wires 0..3 (tan form) ----
    {
        float mt = 1.f;
        #pragma unroll
        for (int k = 0; k < 9; k++)
            mt *= ((t >> k) & 1) ? sx[12 - k] : cx[12 - k];
        int pt = __popc(t);
        #pragma unroll
        for (int r = 0; r < 16; r++) {
            float mr = mt;
            #pragma unroll
            for (int m = 0; m < 4; m++)
                mr *= ((r >> m) & 1) ? sx[3 - m] : cx[3 - m];
            int pr = pt + __popc(r);
            float m0 = mr * cx[13], m1 = mr * sx[13];
            int k0 = pr & 3, k1 = (pr + 1) & 3;
            float re0 = (k0 == 0) ? m0 : ((k0 == 2) ? -m0 : 0.f);
            float im0 = (k0 == 1) ? -m0 : ((k0 == 3) ? m0 : 0.f);
            float re1 = (k1 == 0) ? m1 : ((k1 == 2) ? -m1 : 0.f);
            float im1 = (k1 == 1) ? -m1 : ((k1 == 3) ? m1 : 0.f);
            vre[r] = pk2(re0, im0 == im0 ? re1 : re1); // no-op guard removed below
            vre[r] = pk2(re0, re1); vim[r] = pk2(im0, im1);
        }
        __syncthreads();   // stage-2 LUT writes complete
        #pragma unroll
        for (int lb = 0; lb < 4; lb++) applyW(tanw[3 - lb], lb);
        #pragma unroll
        for (int r = 0; r < 16; r++) { sRe[b1 + 544 * r] = vre[r]; sIm[b1 + 544 * r] = vim[r]; }
    }
    __syncthreads();

    #pragma unroll 1
    for (int L = 0; L < 3; L++) {
        // ---- P2: wires 4..7 ----
        {
            #pragma unroll
            for (int r = 0; r < 16; r++) { vre[r] = sRe[b2 + 34 * r]; vim[r] = sIm[b2 + 34 * r]; }
            #pragma unroll
            for (int lb = 0; lb < 4; lb++) applyW(tanw[L * NQ + (7 - lb)], lb);
            #pragma unroll
            for (int r = 0; r < 16; r++) { sRe[b2 + 34 * r] = vre[r]; sIm[b2 + 34 * r] = vim[r]; }
        }
        __syncwarp(0xffffffffu);   // P2->P3 exchange is warp-local (pair bits 12..9 = warp id)

        // ---- P3: wires 8..11 ----
        {
            #pragma unroll
            for (int r = 0; r < 16; r++) {
                int o = b3 + 2 * r + (r >> 3);
                vre[r] = sRe[o]; vim[r] = sIm[o];
            }
            #pragma unroll
            for (int lb = 0; lb < 4; lb++) applyW(tanw[L * NQ + (11 - lb)], lb);
            #pragma unroll
            for (int r = 0; r < 16; r++) {
                int o = b3 + 2 * r + (r >> 3);
                sRe[o] = vre[r]; sIm[o] = vim[r];
            }
        }
        __syncwarp(0xffffffffu);   // P3->P4 exchange is warp-local

        // ---- P4: wires 12,13; phase for L<2; fused measurement at L=2 ----
        {
            #pragma unroll
            for (int r = 0; r < 16; r++) { vre[r] = sRe[b4 + r]; vim[r] = sIm[b4 + r]; }
            applyW(tanw[L * NQ + 12], 0);
            {
                // wire 13 (lane): v' = v + tm * swp(v), tm = (-t, t)
                ull tm = pk2(-tanw[L * NQ + 13], tanw[L * NQ + 13]);
                #pragma unroll
                for (int r = 0; r < 16; r++) {
                    vre[r] = f2fma(tm, swp(vre[r]), vre[r]);
                    vim[r] = f2fma(tm, swp(vim[r]), vim[r]);
                }
            }
            if (L < 2) {
                float fr = PhiRe[L * 128 + (t >> 2)];
                float fi = PhiIm[L * 128 + (t >> 2)];
                ull fr2 = bc(fr), fi2 = bc(fi), nfi2 = bc(-fi), n1 = bc(-1.f);
                const int c = t & 3;
                #pragma unroll
                for (int r = 0; r < 16; r++) {
                    ull pr2 = PloRe[L * 64 + r * 4 + c];
                    ull pi2 = PloIm[L * 64 + r * 4 + c];
                    ull cr  = f2fma(fr2, pr2, f2mul(nfi2, pi2));
                    ull ci  = f2fma(fr2, pi2, f2mul(fi2, pr2));
                    ull nci = f2mul(n1, ci);
                    ull re = vre[r], im = vim[r];
                    vre[r] = f2fma(cr, re, f2mul(nci, im));
                    vim[r] = f2fma(cr, im, f2mul(ci,  re));
                }
                #pragma unroll
                for (int r = 0; r < 16; r++) { sRe[b4 + r] = vre[r]; sIm[b4 + r] = vim[r]; }
            } else {
                // ---- measurement from registers (chain folded, scaled W) ----
                const int ftt = pf_(t << 5);
                const float whi = Whi[ftt >> 7];
                ull acc2 = bc(0.f);
                #pragma unroll
                for (int k = 0; k < 16; k++) {
                    ull pr2 = f2fma(vim[k], vim[k], f2mul(vre[k], vre[k]));
                    int f0 = (ftt ^ pf_(k << 1)) & 127;
                    float w0 = WloF[f0]     + whi;
                    float w1 = WloF[f0 ^ 1] + whi;
                    acc2 = f2fma(pr2, pk2(w0, w1), acc2);
                }
                float2 ac = upk(acc2);
                float acc = ac.x + ac.y;
                #pragma unroll
                for (int o = 16; o > 0; o >>= 1)
                    acc += __shfl_xor_sync(0xffffffffu, acc, o);
                if ((t & 31) == 0) red[t >> 5] = acc;
                __syncthreads();
                if (t == 0) {
                    float s = 0.f;
                    #pragma unroll
                    for (int w = 0; w < TPB / 32; w++) s += red[w];
                    out[b] = s + hb[0];
                }
            }
        }

        if (L < 2) {
            __syncthreads();   // P4 writes visible block-wide before global fold
            // ---- P1' of next layer with CNOT-chain fold ----
            const int e  = t ^ (t >> 1);
            const int eh = e >> 4;
            #pragma unroll
            for (int r = 0; r < 16; r++) {
                const int C = (r << 1) ^ r;          // compile-time
                int p = e ^ (C << 8);
                int a = p + (eh ^ (C << 4));
                vre[r] = sRe[a]; vim[r] = sIm[a];
            }
            if (t & 1) {
                #pragma unroll
                for (int r = 0; r < 16; r++) { vre[r] = swp(vre[r]); vim[r] = swp(vim[r]); }
            }
            #pragma unroll
            for (int lb = 0; lb < 4; lb++) applyW(tanw[(L + 1) * NQ + (3 - lb)], lb);
            __syncthreads();   // all fold reads done before rewrites
            #pragma unroll
            for (int r = 0; r < 16; r++) { sRe[b1 + 544 * r] = vre[r]; sIm[b1 + 544 * r] = vim[r]; }
            __syncthreads();
        }
    }
}

extern "C" void kernel_launch(void* const* d_in, const int* in_sizes, int n_in,
                              void* d_out, int out_size) {
    const float* sb = (const float*)d_in[0];
    const float* vp = (const float*)d_in[1];
    const float* hw = (const float*)d_in[2];
    const float* hb = (const float*)d_in[3];
    float* out = (float*)d_out;

    const int B = in_sizes[0] / NQ;
    const size_t smem = (size_t)(SPAD * 2 + 128 * 2 + 64) * 8   // sRe,sIm,Plo*,Wlo2
                      + (48 + 48) * 4 + 48 * 8                  // tanw,cosw,phw
                      + (256 * 2 + 32 + 128 + 16) * 4;          // PhiRe/Im,cx,sx,Whi,red
    cudaFuncSetAttribute(qsim_kernel,
                         cudaFuncAttributeMaxDynamicSharedMemorySize, (int)smem);
    qsim_kernel<<<B, TPB, smem>>>(sb, vp, hw, hb, out);
}